// round 9
// baseline (speedup 1.0000x reference)
#include <cuda_runtime.h>
#include <cuda_bf16.h>

#define D 64
#define NT 4
#define N_NODES_MAX 50000
#define N_EDGES_MAX 800000
#define TILE_CAP 1024          // >= ceil(N/64) + NT

typedef unsigned long long ull;

// ---------------- device scratch (~55 MB total) ----------------
__device__ int g_deg[N_NODES_MAX];
__device__ int g_off[N_NODES_MAX + 1];
__device__ int g_cur[N_NODES_MAX];
__device__ int g_ssrc[N_EDGES_MAX];

__device__ int g_tcnt[NT];
__device__ int g_tcur[NT];
__device__ int g_perm[N_NODES_MAX];
__device__ int g_tile_type[TILE_CAP];
__device__ int g_tile_base[TILE_CAP];
__device__ int g_tile_rows[TILE_CAP];

__device__ float4 g_agg4[N_NODES_MAX * 64];   // [n][64] f4 : 16 x-slots + 48 v-slots

// ---------------- packed f32x2 helpers ----------------
__device__ __forceinline__ ull pack2(float a, float b) {
    ull r; asm("mov.b64 %0, {%1,%2};" : "=l"(r) : "f"(a), "f"(b)); return r;
}
__device__ __forceinline__ void ffma2(ull& d, ull a, ull b) {
    asm("fma.rn.f32x2 %0, %1, %2, %0;" : "+l"(d) : "l"(a), "l"(b));
}
__device__ __forceinline__ float2 unpack2(ull v) {
    float2 r; asm("mov.b64 {%0,%1}, %2;" : "=f"(r.x), "=f"(r.y) : "l"(v)); return r;
}

// ---------------- 1) zero counters / tile table ----------------
__global__ void zero_misc_kernel(int n_nodes) {
    int i = blockIdx.x * blockDim.x + threadIdx.x;
    if (i < n_nodes) g_deg[i] = 0;
    if (i < NT) { g_tcnt[i] = 0; g_tcur[i] = 0; }
    if (i < TILE_CAP) g_tile_type[i] = -1;
}

// ---------------- 2) edge in-degree histogram (int4 + tail) ----------------
__global__ void hist_kernel(const int* __restrict__ dst, int n_edges) {
    int n4 = n_edges >> 2;
    int i = blockIdx.x * blockDim.x + threadIdx.x;
    if (i < n4) {
        int4 d = __ldg((const int4*)dst + i);
        atomicAdd(&g_deg[d.x], 1);
        atomicAdd(&g_deg[d.y], 1);
        atomicAdd(&g_deg[d.z], 1);
        atomicAdd(&g_deg[d.w], 1);
    } else if (i == n4) {
        for (int e = n4 << 2; e < n_edges; e++) atomicAdd(&g_deg[dst[e]], 1);
    }
}

// ---------------- 3) node-type histogram ----------------
__global__ void type_hist_kernel(const int* __restrict__ nt, int n_nodes) {
    __shared__ int s[NT];
    if (threadIdx.x < NT) s[threadIdx.x] = 0;
    __syncthreads();
    int i = blockIdx.x * blockDim.x + threadIdx.x;
    if (i < n_nodes) atomicAdd(&s[nt[i]], 1);
    __syncthreads();
    if (threadIdx.x < NT) atomicAdd(&g_tcnt[threadIdx.x], s[threadIdx.x]);
}

// ---------------- 4) CSR exclusive scan (single block) ----------------
__global__ void scan_kernel(int n_nodes) {
    __shared__ int part[1024];
    int tid = threadIdx.x;
    int chunk = (n_nodes + 1023) / 1024;
    int begin = tid * chunk;
    int endi  = min(begin + chunk, n_nodes);

    int s = 0;
    for (int i = begin; i < endi; i++) s += g_deg[i];
    part[tid] = s;
    __syncthreads();
    for (int off = 1; off < 1024; off <<= 1) {
        int v = (tid >= off) ? part[tid - off] : 0;
        __syncthreads();
        part[tid] += v;
        __syncthreads();
    }
    int prefix = (tid > 0) ? part[tid - 1] : 0;
    for (int i = begin; i < endi; i++) {
        int d = g_deg[i];
        g_off[i] = prefix;
        g_cur[i] = prefix;
        prefix += d;
    }
    if (tid == 1023) g_off[n_nodes] = part[1023];
}

// ---------------- 5) type offsets + type-pure tile table ----------------
__global__ void type_scan_kernel(int n_nodes) {
    if (blockIdx.x == 0 && threadIdx.x == 0) {
        int off = 0, tile = 0;
        for (int t = 0; t < NT; t++) {
            int c = g_tcnt[t];
            g_tcur[t] = off;
            for (int r0 = 0; r0 < c; r0 += 64) {
                g_tile_type[tile] = t;
                g_tile_base[tile] = off + r0;
                g_tile_rows[tile] = min(64, c - r0);
                tile++;
            }
            off += c;
        }
    }
}

// ---------------- 6) CSR bucket fill (int4 + tail) ----------------
__global__ void fill_kernel(const int* __restrict__ src,
                            const int* __restrict__ dst, int n_edges) {
    int n4 = n_edges >> 2;
    int i = blockIdx.x * blockDim.x + threadIdx.x;
    if (i < n4) {
        int4 s = __ldg((const int4*)src + i);
        int4 d = __ldg((const int4*)dst + i);
        int p0 = atomicAdd(&g_cur[d.x], 1);
        int p1 = atomicAdd(&g_cur[d.y], 1);
        int p2 = atomicAdd(&g_cur[d.z], 1);
        int p3 = atomicAdd(&g_cur[d.w], 1);
        g_ssrc[p0] = s.x; g_ssrc[p1] = s.y; g_ssrc[p2] = s.z; g_ssrc[p3] = s.w;
    } else if (i == n4) {
        for (int e = n4 << 2; e < n_edges; e++) {
            int pos = atomicAdd(&g_cur[dst[e]], 1);
            g_ssrc[pos] = src[e];
        }
    }
}

// ---------------- 7) perm build (counting-sort by type) ----------------
__global__ void type_fill_kernel(const int* __restrict__ nt, int n_nodes) {
    __shared__ int scnt[NT];
    __shared__ int sbase[NT];
    int tid = threadIdx.x;
    if (tid < NT) scnt[tid] = 0;
    __syncthreads();
    int n = blockIdx.x * blockDim.x + tid;
    int t = 0, local = 0;
    bool ok = (n < n_nodes);
    if (ok) { t = nt[n]; local = atomicAdd(&scnt[t], 1); }
    __syncthreads();
    if (tid < NT) sbase[tid] = atomicAdd(&g_tcur[tid], scnt[tid]);
    __syncthreads();
    if (ok) g_perm[sbase[t] + local] = n;
}

// ---------------- 8) gather: warp-per-node, register accumulation ----------------
__global__ void __launch_bounds__(512, 2)
gather_kernel(const float4* __restrict__ x4,
              const float4* __restrict__ v4, int n_nodes) {
    int warp = (blockIdx.x * blockDim.x + threadIdx.x) >> 5;
    int lane = threadIdx.x & 31;
    int nw   = (gridDim.x * blockDim.x) >> 5;

    for (int n = warp; n < n_nodes; n += nw) {
        int beg = __ldg(g_off + n);
        int end = __ldg(g_off + n + 1);
        float4 acc0 = make_float4(0.f, 0.f, 0.f, 0.f);
        float4 acc1 = make_float4(0.f, 0.f, 0.f, 0.f);

        #pragma unroll 4
        for (int e = beg; e < end; e++) {
            int s = __ldg(g_ssrc + e);
            const float4* p0 = (lane < 16) ? (x4 + (size_t)s * 16 + lane)
                                           : (v4 + (size_t)s * 48 + (lane - 16));
            float4 a = __ldg(p0);
            float4 b = __ldg(v4 + (size_t)s * 48 + 16 + lane);
            acc0.x += a.x; acc0.y += a.y; acc0.z += a.z; acc0.w += a.w;
            acc1.x += b.x; acc1.y += b.y; acc1.z += b.z; acc1.w += b.w;
        }
        g_agg4[(size_t)n * 64 + lane]      = acc0;
        g_agg4[(size_t)n * 64 + 32 + lane] = acc1;
    }
}

// ---------------- 9) type-batched tile GEMM with FFMA2 ----------------
// Block = 64 same-type rows x 256 outputs. 256 threads: r = tid&63 (row),
// q = tid>>6 (16-col group). Weights of this type staged in smem (32 KB),
// A tile staged at stride 257 (conflict-free for staging and reads).
// NOTE: g_agg4 referenced directly from device code (NOT passed from host —
// host-side &g_agg4 is the host shadow and ATS makes it readable as zeros).
__global__ void __launch_bounds__(256, 2)
gemm_kernel(const float* __restrict__ Ws, const float* __restrict__ Wv,
            float* __restrict__ out, int n_nodes) {
    int t = g_tile_type[blockIdx.x];
    if (t < 0) return;
    int base = g_tile_base[blockIdx.x];
    int rows = g_tile_rows[blockIdx.x];

    extern __shared__ float sh[];
    float* sW    = sh;                 // 8192 f: [0,4096)=Ws_t, [4096,8192)=Wv_t
    float* sA    = sh + 8192;          // 64 * 257
    int*   sNode = (int*)(sA + 64 * 257);

    const float* agg = (const float*)g_agg4;   // device-side symbol address

    int tid = threadIdx.x;
    const float4* w0s = (const float4*)(Ws + (size_t)t * 4096);
    const float4* w1s = (const float4*)(Wv + (size_t)t * 4096);
    #pragma unroll
    for (int i = tid; i < 1024; i += 256) {
        ((float4*)sW)[i]        = __ldg(w0s + i);
        ((float4*)sW)[1024 + i] = __ldg(w1s + i);
    }
    if (tid < 64) sNode[tid] = (tid < rows) ? __ldg(g_perm + base + tid) : 0;
    __syncthreads();

    // stage A rows (coalesced LDG, conflict-free STS at stride 257)
    for (int idx = tid; idx < (rows << 8); idx += 256) {
        int row = idx >> 8, col = idx & 255;
        sA[row * 257 + col] = agg[(size_t)sNode[row] * 256 + col];
    }
    __syncthreads();

    int r = tid & 63;
    int q = tid >> 6;
    if (r >= rows) return;
    int node = sNode[r];
    const float* aRow = sA + r * 257;
    int q16 = q * 16;

    // ---- scalar channel: out_s[node] = agg_s @ Ws_t ----
    {
        ull acc[8];
        #pragma unroll
        for (int u = 0; u < 8; u++) acc[u] = 0ULL;
        #pragma unroll 8
        for (int k = 0; k < 64; k++) {
            float av = aRow[k];
            ull a2 = pack2(av, av);
            const ulonglong2* wp = (const ulonglong2*)(sW + k * 64 + q16);
            ulonglong2 w0 = wp[0], w1 = wp[1], w2 = wp[2], w3 = wp[3];
            ffma2(acc[0], a2, w0.x); ffma2(acc[1], a2, w0.y);
            ffma2(acc[2], a2, w1.x); ffma2(acc[3], a2, w1.y);
            ffma2(acc[4], a2, w2.x); ffma2(acc[5], a2, w2.y);
            ffma2(acc[6], a2, w3.x); ffma2(acc[7], a2, w3.y);
        }
        float2* o = (float2*)(out + (size_t)node * 64 + q16);
        #pragma unroll
        for (int u = 0; u < 8; u++) o[u] = unpack2(acc[u]);
    }

    // ---- vector channels (3x, sharing each Wv load) ----
    {
        ull ac0[8], ac1[8], ac2[8];
        #pragma unroll
        for (int u = 0; u < 8; u++) { ac0[u] = 0ULL; ac1[u] = 0ULL; ac2[u] = 0ULL; }
        const float* wV = sW + 4096;
        #pragma unroll 4
        for (int k = 0; k < 64; k++) {
            float a0 = aRow[64 + k], a1 = aRow[128 + k], a2v = aRow[192 + k];
            ull p0 = pack2(a0, a0), p1 = pack2(a1, a1), p2 = pack2(a2v, a2v);
            const ulonglong2* wp = (const ulonglong2*)(wV + k * 64 + q16);
            ulonglong2 w0 = wp[0], w1 = wp[1], w2 = wp[2], w3 = wp[3];
            ffma2(ac0[0], p0, w0.x); ffma2(ac0[1], p0, w0.y);
            ffma2(ac0[2], p0, w1.x); ffma2(ac0[3], p0, w1.y);
            ffma2(ac0[4], p0, w2.x); ffma2(ac0[5], p0, w2.y);
            ffma2(ac0[6], p0, w3.x); ffma2(ac0[7], p0, w3.y);
            ffma2(ac1[0], p1, w0.x); ffma2(ac1[1], p1, w0.y);
            ffma2(ac1[2], p1, w1.x); ffma2(ac1[3], p1, w1.y);
            ffma2(ac1[4], p1, w2.x); ffma2(ac1[5], p1, w2.y);
            ffma2(ac1[6], p1, w3.x); ffma2(ac1[7], p1, w3.y);
            ffma2(ac2[0], p2, w0.x); ffma2(ac2[1], p2, w0.y);
            ffma2(ac2[2], p2, w1.x); ffma2(ac2[3], p2, w1.y);
            ffma2(ac2[4], p2, w2.x); ffma2(ac2[5], p2, w2.y);
            ffma2(ac2[6], p2, w3.x); ffma2(ac2[7], p2, w3.y);
        }
        float* ov = out + (size_t)n_nodes * 64 + (size_t)node * 192 + q16;
        float2* o0 = (float2*)(ov);
        float2* o1 = (float2*)(ov + 64);
        float2* o2 = (float2*)(ov + 128);
        #pragma unroll
        for (int u = 0; u < 8; u++) {
            o0[u] = unpack2(ac0[u]);
            o1[u] = unpack2(ac1[u]);
            o2[u] = unpack2(ac2[u]);
        }
    }
}

// ---------------- launch ----------------
extern "C" void kernel_launch(void* const* d_in, const int* in_sizes, int n_in,
                              void* d_out, int out_size) {
    const float* x   = (const float*)d_in[0];
    const float* vec = (const float*)d_in[1];
    const int*   nty = (const int*)d_in[2];
    const int*   src = (const int*)d_in[3];
    const int*   dst = (const int*)d_in[4];
    const float* Ws  = (const float*)d_in[5];
    const float* Wv  = (const float*)d_in[6];
    float* out = (float*)d_out;

    int n_nodes = in_sizes[2];
    int n_edges = in_sizes[3];
    int e4 = (n_edges >> 2) + 1;          // +1 thread for tail

    zero_misc_kernel<<<(n_nodes + 255) / 256, 256>>>(n_nodes);
    hist_kernel<<<(e4 + 255) / 256, 256>>>(dst, n_edges);
    type_hist_kernel<<<(n_nodes + 255) / 256, 256>>>(nty, n_nodes);
    scan_kernel<<<1, 1024>>>(n_nodes);
    type_scan_kernel<<<1, 32>>>(n_nodes);
    fill_kernel<<<(e4 + 255) / 256, 256>>>(src, dst, n_edges);
    type_fill_kernel<<<(n_nodes + 255) / 256, 256>>>(nty, n_nodes);

    gather_kernel<<<296, 512>>>((const float4*)x, (const float4*)vec, n_nodes);

    int n_tiles_cap = (n_nodes + 63) / 64 + NT;   // <= TILE_CAP
    size_t smem = (size_t)(8192 + 64 * 257) * sizeof(float) + 64 * sizeof(int);
    static bool attr_set = false;
    if (!attr_set) {
        cudaFuncSetAttribute(gemm_kernel,
                             cudaFuncAttributeMaxDynamicSharedMemorySize,
                             (int)smem);
        attr_set = true;
    }
    gemm_kernel<<<n_tiles_cap, 256, smem>>>(Ws, Wv, out, n_nodes);
}

// round 10
// speedup vs baseline: 2.3602x; 2.3602x over previous
#include <cuda_runtime.h>
#include <cuda_bf16.h>

#define D 64
#define NT 4
#define N_NODES_MAX 50000
#define N_EDGES_MAX 800000

// ---------------- device scratch ----------------
__device__ int g_deg[N_NODES_MAX];
__device__ int g_off[N_NODES_MAX];
__device__ int g_cur[N_NODES_MAX];
__device__ int g_ssrc[N_EDGES_MAX];
__device__ int g_total;

// ---------------- 1) zero degree counters ----------------
__global__ void zero_kernel(int n_nodes) {
    int i = blockIdx.x * blockDim.x + threadIdx.x;
    if (i < n_nodes) g_deg[i] = 0;
    if (i == 0) g_total = 0;
}

// ---------------- 2) in-degree histogram (int4 + tail) ----------------
__global__ void hist_kernel(const int* __restrict__ dst, int n_edges) {
    int n4 = n_edges >> 2;
    int i = blockIdx.x * blockDim.x + threadIdx.x;
    if (i < n4) {
        int4 d = __ldg((const int4*)dst + i);
        atomicAdd(&g_deg[d.x], 1);
        atomicAdd(&g_deg[d.y], 1);
        atomicAdd(&g_deg[d.z], 1);
        atomicAdd(&g_deg[d.w], 1);
    } else if (i == n4) {
        for (int e = n4 << 2; e < n_edges; e++) atomicAdd(&g_deg[dst[e]], 1);
    }
}

// ---------------- 3) bucket range assignment (NO prefix scan) ----------------
// Bucket order is irrelevant for correctness -- only disjointness. Each warp
// scans its 32 degrees with shfl, grabs a range with ONE atomicAdd, and
// derives per-node offsets. Replaces the 82.8us single-block scan.
__global__ void offsets_kernel(int n_nodes) {
    int i    = blockIdx.x * blockDim.x + threadIdx.x;
    int lane = threadIdx.x & 31;
    int d    = (i < n_nodes) ? g_deg[i] : 0;

    int incl = d;
    #pragma unroll
    for (int o = 1; o < 32; o <<= 1) {
        int v = __shfl_up_sync(0xFFFFFFFFu, incl, o);
        if (lane >= o) incl += v;
    }
    int wsum = __shfl_sync(0xFFFFFFFFu, incl, 31);
    int base = 0;
    if (lane == 31) base = atomicAdd(&g_total, wsum);
    base = __shfl_sync(0xFFFFFFFFu, base, 31);

    if (i < n_nodes) {
        int off = base + incl - d;
        g_off[i] = off;
        g_cur[i] = off;
    }
}

// ---------------- 4) CSR bucket fill (int4 + tail) ----------------
__global__ void fill_kernel(const int* __restrict__ src,
                            const int* __restrict__ dst, int n_edges) {
    int n4 = n_edges >> 2;
    int i = blockIdx.x * blockDim.x + threadIdx.x;
    if (i < n4) {
        int4 s = __ldg((const int4*)src + i);
        int4 d = __ldg((const int4*)dst + i);
        int p0 = atomicAdd(&g_cur[d.x], 1);
        int p1 = atomicAdd(&g_cur[d.y], 1);
        int p2 = atomicAdd(&g_cur[d.z], 1);
        int p3 = atomicAdd(&g_cur[d.w], 1);
        g_ssrc[p0] = s.x; g_ssrc[p1] = s.y; g_ssrc[p2] = s.z; g_ssrc[p3] = s.w;
    } else if (i == n4) {
        for (int e = n4 << 2; e < n_edges; e++) {
            int pos = atomicAdd(&g_cur[dst[e]], 1);
            g_ssrc[pos] = src[e];
        }
    }
}

// ---------------- 5) fused gather + per-type projection (R7 kernel) --------
// Warp per node: accumulate the 256-float agg row in registers from the
// node's bucket (no atomics), stage to shared, then 4 matvecs against the
// node-type's weights (all 8 matrices staged once per block, 128 KB smem).
__global__ void __launch_bounds__(1024, 1)
fused_kernel(const int*    __restrict__ node_type,
             const float*  __restrict__ Ws,
             const float*  __restrict__ Wv,
             const float4* __restrict__ x4,
             const float4* __restrict__ v4,
             float*        __restrict__ out,
             int n_nodes) {
    extern __shared__ float sh[];
    float* sWs  = sh;                     // NT*4096 floats
    float* sWv  = sh + NT * 4096;         // NT*4096 floats
    float* sAgg = sh + 2 * NT * 4096;     // nwarps * 256 floats

    int tid = threadIdx.x;
    const float4* Ws4 = (const float4*)Ws;
    const float4* Wv4 = (const float4*)Wv;
    for (int i = tid; i < NT * 1024; i += blockDim.x) {
        ((float4*)sWs)[i] = __ldg(Ws4 + i);
        ((float4*)sWv)[i] = __ldg(Wv4 + i);
    }
    __syncthreads();

    int warp   = tid >> 5;
    int lane   = tid & 31;
    int nwarps = blockDim.x >> 5;
    float* myAgg = sAgg + warp * 256;
    float* out_v = out + (size_t)n_nodes * 64;

    for (int n = blockIdx.x * nwarps + warp; n < n_nodes;
         n += gridDim.x * nwarps) {
        int beg = __ldg(g_off + n);
        int end = beg + __ldg(g_deg + n);

        float4 acc0 = make_float4(0.f, 0.f, 0.f, 0.f);
        float4 acc1 = make_float4(0.f, 0.f, 0.f, 0.f);

        #pragma unroll 4
        for (int e = beg; e < end; e++) {
            int s = __ldg(g_ssrc + e);
            const float4* p0 = (lane < 16) ? (x4 + (size_t)s * 16 + lane)
                                           : (v4 + (size_t)s * 48 + (lane - 16));
            float4 a = __ldg(p0);
            float4 b = __ldg(v4 + (size_t)s * 48 + 16 + lane);
            acc0.x += a.x; acc0.y += a.y; acc0.z += a.z; acc0.w += a.w;
            acc1.x += b.x; acc1.y += b.y; acc1.z += b.z; acc1.w += b.w;
        }

        ((float4*)myAgg)[lane]      = acc0;
        ((float4*)myAgg)[32 + lane] = acc1;
        __syncwarp();

        int t = __ldg(node_type + n);
        const float* ws = sWs + t * 4096;
        const float* wv = sWv + t * 4096;

        float2 accs  = make_float2(0.f, 0.f);
        float2 accv0 = make_float2(0.f, 0.f);
        float2 accv1 = make_float2(0.f, 0.f);
        float2 accv2 = make_float2(0.f, 0.f);

        #pragma unroll 8
        for (int k = 0; k < 64; k++) {
            float a_s  = myAgg[k];
            float a_v0 = myAgg[64  + k];
            float a_v1 = myAgg[128 + k];
            float a_v2 = myAgg[192 + k];
            float2 w_s = ((const float2*)(ws + k * 64))[lane];
            float2 w_v = ((const float2*)(wv + k * 64))[lane];
            accs.x  = fmaf(a_s,  w_s.x, accs.x);
            accs.y  = fmaf(a_s,  w_s.y, accs.y);
            accv0.x = fmaf(a_v0, w_v.x, accv0.x);
            accv0.y = fmaf(a_v0, w_v.y, accv0.y);
            accv1.x = fmaf(a_v1, w_v.x, accv1.x);
            accv1.y = fmaf(a_v1, w_v.y, accv1.y);
            accv2.x = fmaf(a_v2, w_v.x, accv2.x);
            accv2.y = fmaf(a_v2, w_v.y, accv2.y);
        }

        ((float2*)(out + (size_t)n * 64))[lane]          = accs;
        ((float2*)(out_v + (size_t)n * 192))[lane]       = accv0;
        ((float2*)(out_v + (size_t)n * 192 + 64))[lane]  = accv1;
        ((float2*)(out_v + (size_t)n * 192 + 128))[lane] = accv2;
        __syncwarp();   // protect myAgg before next node restages
    }
}

// ---------------- launch ----------------
extern "C" void kernel_launch(void* const* d_in, const int* in_sizes, int n_in,
                              void* d_out, int out_size) {
    const float* x   = (const float*)d_in[0];
    const float* vec = (const float*)d_in[1];
    const int*   nty = (const int*)d_in[2];
    const int*   src = (const int*)d_in[3];
    const int*   dst = (const int*)d_in[4];
    const float* Ws  = (const float*)d_in[5];
    const float* Wv  = (const float*)d_in[6];
    float* out = (float*)d_out;

    int n_nodes = in_sizes[2];
    int n_edges = in_sizes[3];
    int e4 = (n_edges >> 2) + 1;          // +1 thread for tail

    zero_kernel<<<(n_nodes + 255) / 256, 256>>>(n_nodes);
    hist_kernel<<<(e4 + 255) / 256, 256>>>(dst, n_edges);
    offsets_kernel<<<(n_nodes + 255) / 256, 256>>>(n_nodes);
    fill_kernel<<<(e4 + 255) / 256, 256>>>(src, dst, n_edges);

    const int threads = 1024;
    const int nwarps  = threads / 32;
    size_t smem = (size_t)(2 * NT * 4096 + nwarps * 256) * sizeof(float); // 160 KB
    static bool attr_set = false;
    if (!attr_set) {
        cudaFuncSetAttribute(fused_kernel,
                             cudaFuncAttributeMaxDynamicSharedMemorySize,
                             (int)smem);
        attr_set = true;
    }
    fused_kernel<<<148, threads, smem>>>(
        nty, Ws, Wv, (const float4*)x, (const float4*)vec, out, n_nodes);
}